// round 16
// baseline (speedup 1.0000x reference)
#include <cuda_runtime.h>
#include <cuda_fp16.h>
#include <cstdint>

// Conv2D 4096x4096, 15x15, pad=1 -> 4084x4084, + bias.
// R16: R15 (k16 MMAs + shared k8 B-fragments, 5 LDS.32/dy) with the window
// rotation cut to 2 buffers -> 42 regs -> launch_bounds(256,6): 6 CTAs/SM,
// 48 warps. Running pointers kill per-dy address ALU.

#define KS      15
#define IN_N    4096
#define OUT_N   4084
#define CTA_Y   64             // 4 warps in y, 16 rows each
#define CTA_X   96             // 2 warps in x, 48 cols each
#define AROWS   78             // 64 + 14 halo
#define ACOLS   110            // 96 + 14 halo (cols [110,120) zero pad)
#define ASTRIDE 120            // fp16/row; 240B rows, 240/16=15 odd -> ldm conflict-free
#define NDY     KS
#define NF8     5              // distinct k8 fragments per dy (shifts -8,0,+8,+16,+24)

__device__ uint32_t gBf[NDY * NF8 * 32];   // k8 fragments in mma lane layout

// f[d], lane: t = 8*(d-1) + 2*(lane&3) + {0,1} - (lane>>2)
__global__ void prep_Bfrag(const float* __restrict__ w)
{
    int idx = blockIdx.x * blockDim.x + threadIdx.x;
    if (idx >= NDY * NF8 * 32) return;
    const int lane = idx & 31;
    const int d    = (idx / 32) % NF8;
    const int dy   = idx / (32 * NF8);
    const int tg   = lane & 3;
    const int gp   = lane >> 2;
    const int base = 8 * (d - 1) + 2 * tg - gp;
    float v0 = 0.0f, v1 = 0.0f;
    if (base >= 0     && base < KS)     v0 = w[dy * KS + base];
    if (base + 1 >= 0 && base + 1 < KS) v1 = w[dy * KS + base + 1];
    __half2 h = __floats2half2_rn(v0, v1);
    gBf[idx] = *reinterpret_cast<uint32_t*>(&h);
}

__device__ __forceinline__ uint32_t smem_u32(const void* p)
{
    uint32_t a;
    asm("{ .reg .u64 t; cvta.to.shared.u64 t, %1; cvt.u32.u64 %0, t; }"
        : "=r"(a) : "l"(p));
    return a;
}
__device__ __forceinline__ void ldmA(uint32_t a[4], uint32_t addr)
{
    asm volatile("ldmatrix.sync.aligned.m8n8.x4.shared.b16 {%0,%1,%2,%3}, [%4];"
                 : "=r"(a[0]), "=r"(a[1]), "=r"(a[2]), "=r"(a[3]) : "r"(addr));
}
__device__ __forceinline__ void mma16816(float c[4], const uint32_t a[4],
                                         uint32_t b0, uint32_t b1)
{
    asm volatile(
        "mma.sync.aligned.m16n8k16.row.col.f32.f16.f16.f32 "
        "{%0,%1,%2,%3}, {%4,%5,%6,%7}, {%8,%9}, {%0,%1,%2,%3};"
        : "+f"(c[0]), "+f"(c[1]), "+f"(c[2]), "+f"(c[3])
        : "r"(a[0]), "r"(a[1]), "r"(a[2]), "r"(a[3]), "r"(b0), "r"(b1));
}

__global__ __launch_bounds__(256, 6)
void conv2d_mma_r16_kernel(const float* __restrict__ x,
                           const float* __restrict__ bias,
                           float* __restrict__ out)
{
    __shared__ __align__(32) __half sA[AROWS * ASTRIDE];   // 18720 B
    __shared__ uint32_t sBf[NDY * NF8 * 32];               // 9600 B

    const int tid  = threadIdx.x;
    const int lane = tid & 31;
    const int wid  = tid >> 5;
    const int wy   = wid >> 1;          // 0..3 (16 rows each)
    const int wx   = wid & 1;           // 0..1 (48 cols each)
    const int X0   = blockIdx.x * CTA_X;
    const int Y0   = blockIdx.y * CTA_Y;

    // ---- stage B fragments ----
    for (int i = tid; i < NDY * NF8 * 32; i += 256)
        sBf[i] = gBf[i];

    // ---- stage A: 78 x 110 fp32 -> fp16 (smem col j <-> input col X0-1+j);
    //      cols [110, 120) zero-filled ----
    for (int idx = tid; idx < AROWS * (ASTRIDE / 2); idx += 256) {
        const int r  = idx / (ASTRIDE / 2);
        const int p  = idx - r * (ASTRIDE / 2);
        const int c  = 2 * p;
        const int gy = Y0 - 1 + r;
        const int gx = X0 - 1 + c;
        float v0 = 0.0f, v1 = 0.0f;
        if (c < ACOLS && (unsigned)gy < IN_N) {
            const float* rp = x + (size_t)gy * IN_N;
            if ((unsigned)gx       < IN_N) v0 = rp[gx];
            if ((unsigned)(gx + 1) < IN_N && c + 1 < ACOLS) v1 = rp[gx + 1];
        }
        *reinterpret_cast<__half2*>(&sA[r * ASTRIDE + c]) = __floats2half2_rn(v0, v1);
    }
    __syncthreads();

    // ---- accumulators seeded with bias (6 n-blocks x 4) ----
    const float bval = bias[0];
    float acc[6][4];
    #pragma unroll
    for (int j = 0; j < 6; ++j)
        #pragma unroll
        for (int e = 0; e < 4; ++e)
            acc[j][e] = bval;

    const uint32_t sA_b = smem_u32(sA);
    // running pointers (incremented per dy, no per-iteration IMAD chains)
    uint32_t rrow = sA_b + (uint32_t)((lane & 15) * (ASTRIDE * 2))
                  + (uint32_t)(96 * wx) + (uint32_t)((lane >> 4) << 4)
                  + (uint32_t)(16 * wy * (ASTRIDE * 2));
    uint32_t abB  = smem_u32(sBf) + (uint32_t)(lane * 4);

    #pragma unroll 1
    for (int dy = 0; dy < NDY; ++dy) {
        // --- batch: 5 B LDS.32 + first two windows, MLP = 7 ---
        uint32_t f0, f1, f2, f3, f4;
        asm volatile("ld.shared.u32 %0, [%1];" : "=r"(f0) : "r"(abB));
        asm volatile("ld.shared.u32 %0, [%1];" : "=r"(f1) : "r"(abB + 1 * 128));
        asm volatile("ld.shared.u32 %0, [%1];" : "=r"(f2) : "r"(abB + 2 * 128));
        asm volatile("ld.shared.u32 %0, [%1];" : "=r"(f3) : "r"(abB + 3 * 128));
        asm volatile("ld.shared.u32 %0, [%1];" : "=r"(f4) : "r"(abB + 4 * 128));
        uint32_t wA[4], wB[4];
        ldmA(wA, rrow);          // w0: cols  0-15
        ldmA(wB, rrow + 32);     // w1: cols 16-31

        // --- nb0, nb1 (w0, w1) ---
        mma16816(acc[0], wA, f1, f2);      // b[1]
        mma16816(acc[0], wB, f3, f4);      // b[3]
        mma16816(acc[1], wA, f0, f1);      // b[0]
        mma16816(acc[1], wB, f2, f3);      // b[2]

        ldmA(wA, rrow + 64);     // w2: cols 32-47 (5 MMAs before first use)

        // --- nb2, nb3 (w1, w2) ---
        mma16816(acc[2], wB, f1, f2);
        mma16816(acc[2], wA, f3, f4);
        mma16816(acc[3], wB, f0, f1);
        mma16816(acc[3], wA, f2, f3);

        ldmA(wB, rrow + 96);     // w3: cols 48-63

        // --- nb4, nb5 (w2, w3) ---
        mma16816(acc[4], wA, f1, f2);
        mma16816(acc[4], wB, f3, f4);
        mma16816(acc[5], wA, f0, f1);
        mma16816(acc[5], wB, f2, f3);

        rrow += (uint32_t)(ASTRIDE * 2);
        abB  += (uint32_t)(NF8 * 128);
    }

    // ---- epilogue: D fragments -> gmem (float2 stores) ----
    const int tg = lane & 3;
    const int gp = lane >> 2;
    #pragma unroll
    for (int j = 0; j < 6; ++j) {
        const int col = X0 + 48 * wx + 8 * j + 2 * tg;
        const int r0  = Y0 + 16 * wy + gp;
        if (col < OUT_N) {
            if (r0 < OUT_N) {
                float2 v = make_float2(acc[j][0], acc[j][1]);
                *reinterpret_cast<float2*>(&out[(size_t)r0 * OUT_N + col]) = v;
            }
            if (r0 + 8 < OUT_N) {
                float2 v = make_float2(acc[j][2], acc[j][3]);
                *reinterpret_cast<float2*>(&out[(size_t)(r0 + 8) * OUT_N + col]) = v;
            }
        }
    }
}

extern "C" void kernel_launch(void* const* d_in, const int* in_sizes, int n_in,
                              void* d_out, int out_size)
{
    const float* x    = (const float*)d_in[0];   // 4096*4096
    const float* w    = (const float*)d_in[1];   // 15*15
    const float* bias = (const float*)d_in[2];   // 1
    float* out        = (float*)d_out;           // 4084*4084

    prep_Bfrag<<<(NDY * NF8 * 32 + 255) / 256, 256>>>(w);

    dim3 grid((OUT_N + CTA_X - 1) / CTA_X,       // 43
              (OUT_N + CTA_Y - 1) / CTA_Y);      // 64
    conv2d_mma_r16_kernel<<<grid, 256>>>(x, bias, out);
}